// round 13
// baseline (speedup 1.0000x reference)
#include <cuda_runtime.h>
#include <cuda_bf16.h>
#include <cstdint>

#define BT 6
#define NN 4096
#define DD 64
#define WC 8192

typedef unsigned long long u64;

// Scratch (device globals — no allocations allowed)
__device__ float    g_mii [BT*NN];
__device__ uint32_t g_Eh32[BT*NN*32];        // E hi (bf16x2 along d)
__device__ uint32_t g_El32[BT*NN*32];        // E lo
__device__ uint32_t g_Xth [BT*DD*(NN/2)];    // X^T hi: [bt*64+d][k/2]
__device__ uint32_t g_Xtl [BT*DD*(NN/2)];    // X^T lo
__device__ uint32_t g_Ah  [NN*32];           // node_emb hi (bf16x2 along d)
__device__ uint32_t g_Al  [NN*32];           // node_emb lo
__device__ uint32_t g_Bph [WC*32];           // wpool^T hi: [c][d/2]
__device__ uint32_t g_Bpl [WC*32];           // wpool^T lo
__device__ float    g_W   [(size_t)NN*WC];   // hypernet weights, 134 MB
__device__ float    g_pacc[2][BT*NN*DD];     // attention partial numerators
__device__ float    g_pden[2][BT*NN];        // attention partial denominators
__device__ float    g_bias[BT*DD];

// ---------------- helpers ----------------
__device__ __forceinline__ uint32_t pkbf(float a, float b) {
    __nv_bfloat162 t; t.x = __float2bfloat16(a); t.y = __float2bfloat16(b);
    return *reinterpret_cast<uint32_t*>(&t);
}
__device__ __forceinline__ void split2(float a, float b, uint32_t& hi, uint32_t& lo) {
    __nv_bfloat16 ha = __float2bfloat16(a), hb = __float2bfloat16(b);
    __nv_bfloat162 hp; hp.x = ha; hp.y = hb;
    hi = *reinterpret_cast<uint32_t*>(&hp);
    lo = pkbf(a - __bfloat162float(ha), b - __bfloat162float(hb));
}
__device__ __forceinline__ void mma16816(float* c, const uint32_t* a, uint32_t b0, uint32_t b1) {
    asm volatile(
        "mma.sync.aligned.m16n8k16.row.col.f32.bf16.bf16.f32 "
        "{%0,%1,%2,%3}, {%4,%5,%6,%7}, {%8,%9}, {%0,%1,%2,%3};"
        : "+f"(c[0]), "+f"(c[1]), "+f"(c[2]), "+f"(c[3])
        : "r"(a[0]), "r"(a[1]), "r"(a[2]), "r"(a[3]), "r"(b0), "r"(b1));
}
// load 4 8x8 b16 matrices; lane l supplies row (l&7) addr of matrix (l>>3)
__device__ __forceinline__ void ldm4(uint32_t* r, uint32_t saddr) {
    asm volatile("ldmatrix.sync.aligned.m8n8.x4.shared.b16 {%0,%1,%2,%3}, [%4];"
        : "=r"(r[0]), "=r"(r[1]), "=r"(r[2]), "=r"(r[3]) : "r"(saddr));
}
__device__ __forceinline__ uint32_t s2u(const void* p) {
    return (uint32_t)__cvta_generic_to_shared(p);
}
__device__ __forceinline__ void cpa16(void* dst, const void* src) {
    uint32_t d = (uint32_t)__cvta_generic_to_shared(dst);
    asm volatile("cp.async.ca.shared.global [%0], [%1], 16;" :: "r"(d), "l"(src));
}
#define CP_COMMIT() asm volatile("cp.async.commit_group;" ::: "memory")
#define CP_WAIT1()  asm volatile("cp.async.wait_group 1;" ::: "memory")

// ---------------- K1: LayerNorm -> bf16 hi/lo + mii (+node_emb split) ------
__global__ __launch_bounds__(256) void k_ln(
    const float* __restrict__ ne, const float* __restrict__ te,
    const float* __restrict__ gamma, const float* __restrict__ beta)
{
    int row = blockIdx.x * 8 + (threadIdx.x >> 5);
    int lane = threadIdx.x & 31;
    int bt = row >> 12, n = row & (NN - 1);
    float2 nv = *(const float2*)(ne + n * DD + 2 * lane);
    float2 tv = *(const float2*)(te + bt * DD + 2 * lane);

    if (bt == 0) {
        uint32_t hi, lo;
        split2(nv.x, nv.y, hi, lo);
        g_Ah[n * 32 + lane] = hi;
        g_Al[n * 32 + lane] = lo;
    }

    float e0 = nv.x + tv.x, e1 = nv.y + tv.y;
    float s = e0 + e1, s2 = e0 * e0 + e1 * e1;
    #pragma unroll
    for (int o = 16; o; o >>= 1) {
        s  += __shfl_xor_sync(~0u, s,  o);
        s2 += __shfl_xor_sync(~0u, s2, o);
    }
    float mu = s * (1.f / 64.f), var = s2 * (1.f / 64.f) - mu * mu;
    float rs = rsqrtf(var + 1e-12f);
    float o0 = (e0 - mu) * rs * gamma[2 * lane]     + beta[2 * lane];
    float o1 = (e1 - mu) * rs * gamma[2 * lane + 1] + beta[2 * lane + 1];
    uint32_t hi, lo;
    split2(o0, o1, hi, lo);
    g_Eh32[row * 32 + lane] = hi;
    g_El32[row * 32 + lane] = lo;
    float q2 = o0 * o0 + o1 * o1;
    #pragma unroll
    for (int o = 16; o; o >>= 1) q2 += __shfl_xor_sync(~0u, q2, o);
    if (lane == 0) g_mii[row] = q2;
}

// ---------------- K1b: X -> X^T bf16 hi/lo ----------------
__global__ __launch_bounds__(256) void k_xsplit(const float* __restrict__ x)
{
    __shared__ float t[64][65];
    int bt = blockIdx.y, k0 = blockIdx.x * 64;
    for (int i = threadIdx.x; i < 4096; i += 256)
        t[i >> 6][i & 63] = x[((size_t)bt * NN + k0 + (i >> 6)) * DD + (i & 63)];
    __syncthreads();
    for (int i = threadIdx.x; i < 2048; i += 256) {
        int d = i >> 5, c2 = i & 31;
        uint32_t hi, lo;
        split2(t[c2 * 2][d], t[c2 * 2 + 1][d], hi, lo);
        size_t gi = (size_t)(bt * DD + d) * (NN / 2) + k0 / 2 + c2;
        g_Xth[gi] = hi;
        g_Xtl[gi] = lo;
    }
}

// ---------------- K1d: wpool -> transposed bf16 hi/lo [c][d/2]  (+bias) -----
__global__ __launch_bounds__(256) void k_wpsplit(
    const float* __restrict__ wp, const float* __restrict__ te,
    const float* __restrict__ bp)
{
    __shared__ float t[64][33];
    int c0 = blockIdx.x * 32;
    for (int i = threadIdx.x; i < 2048; i += 256)
        t[i >> 5][i & 31] = wp[(size_t)(i >> 5) * WC + c0 + (i & 31)];
    __syncthreads();
    for (int i = threadIdx.x; i < 1024; i += 256) {
        int c = i >> 5, dp = i & 31;
        uint32_t hi, lo;
        split2(t[dp * 2][c], t[dp * 2 + 1][c], hi, lo);
        g_Bph[(size_t)(c0 + c) * 32 + dp] = hi;
        g_Bpl[(size_t)(c0 + c) * 32 + dp] = lo;
    }
    if (blockIdx.x == 0) {   // folded bias: bias[bt,o] = te[bt,:].bp[:,o]
        for (int i = threadIdx.x; i < BT * DD; i += 256) {
            int bt = i >> 6, o = i & 63;
            float s = 0.f;
            #pragma unroll
            for (int d = 0; d < DD; d++) s += te[bt * DD + d] * bp[d * DD + o];
            g_bias[i] = s;
        }
    }
}

// ---------------- K4: HMMA attention, 256 thr / 128 queries per block ------
__global__ __launch_bounds__(256) void k_attn_mma()
{
    __shared__ __align__(16) uint32_t sEh[2][32][36], sEl[2][32][36];
    __shared__ __align__(16) uint32_t sXh[2][64][20], sXl[2][64][20];

    const int tid = threadIdx.x, w = tid >> 5, l = tid & 31;
    const int tig = l & 3, gr = l >> 2;
    const int bt = blockIdx.y;
    const int q0 = blockIdx.x * 128;
    const int kh = blockIdx.z;
    const int k0 = kh * (NN / 2);

    const size_t qrow = (size_t)(bt * NN + q0 + w * 16 + gr);
    uint32_t Qh[4][4], Ql[4][4];
    #pragma unroll
    for (int kc = 0; kc < 4; kc++) {
        int c0 = kc * 8 + tig, c1 = kc * 8 + 4 + tig;
        Qh[kc][0] = g_Eh32[qrow * 32 + c0];
        Qh[kc][1] = g_Eh32[(qrow + 8) * 32 + c0];
        Qh[kc][2] = g_Eh32[qrow * 32 + c1];
        Qh[kc][3] = g_Eh32[(qrow + 8) * 32 + c1];
        Ql[kc][0] = g_El32[qrow * 32 + c0];
        Ql[kc][1] = g_El32[(qrow + 8) * 32 + c0];
        Ql[kc][2] = g_El32[qrow * 32 + c1];
        Ql[kc][3] = g_El32[(qrow + 8) * 32 + c1];
    }
    const float mii0 = g_mii[qrow];
    const float mii1 = g_mii[qrow + 8];

    const uint32_t aEh = s2u(&sEh[0][l][0]);   // + b*4608
    const uint32_t aEl = s2u(&sEl[0][l][0]);
    const uint32_t aXh = s2u(&sXh[0][l][0]);   // + b*5120 (+2560 for dg=1)
    const uint32_t aXl = s2u(&sXl[0][l][0]);

    float acc[8][4];
    #pragma unroll
    for (int i = 0; i < 8; i++)
        #pragma unroll
        for (int j = 0; j < 4; j++) acc[i][j] = 0.f;
    float den0 = 0.f, den1 = 0.f;

    auto prefetch = [&](int t) {
        if (t < 64) {
            int b = t & 1, m = k0 + t * 32;
            if (tid < 256) {   // one element per thread per tile set
                {
                    int i = tid;                     // E tiles: 32 rows x 8 chunks
                    int r = i >> 3, c = (i & 7) << 2;
                    size_t g = (size_t)(bt * NN + m + r) * 32 + c;
                    cpa16(&sEh[b][r][c], g_Eh32 + g);
                    cpa16(&sEl[b][r][c], g_El32 + g);
                }
                {
                    int i = tid;                     // X tiles: 64 rows x 4 chunks
                    int r = i >> 2, c = (i & 3) << 2;
                    size_t g = (size_t)(bt * DD + r) * (NN / 2) + (m >> 1) + c;
                    cpa16(&sXh[b][r][c], g_Xth + g);
                    cpa16(&sXl[b][r][c], g_Xtl + g);
                }
            }
        }
        CP_COMMIT();
    };

    prefetch(0);

    for (int t = 0; t < 64; t++) {
        prefetch(t + 1);
        CP_WAIT1();
        __syncthreads();

        const uint32_t bEh = aEh + (t & 1) * 4608;
        const uint32_t bEl = aEl + (t & 1) * 4608;
        const uint32_t bXh = aXh + (t & 1) * 5120;
        const uint32_t bXl = aXl + (t & 1) * 5120;

        // S = Eq . Ek^T
        float sacc[4][4];
        #pragma unroll
        for (int i = 0; i < 4; i++)
            #pragma unroll
            for (int j = 0; j < 4; j++) sacc[i][j] = 0.f;
        #pragma unroll
        for (int kc = 0; kc < 4; kc++) {
            uint32_t bh0[4], bh1[4], bl0[4], bl1[4];
            ldm4(bh0, bEh + kc * 32);
            ldm4(bh1, bEh + kc * 32 + 16);
            ldm4(bl0, bEl + kc * 32);
            ldm4(bl1, bEl + kc * 32 + 16);
            #pragma unroll
            for (int nt = 0; nt < 4; nt++) {
                mma16816(sacc[nt], Qh[kc], bh0[nt], bh1[nt]);
                mma16816(sacc[nt], Qh[kc], bl0[nt], bl1[nt]);
                mma16816(sacc[nt], Ql[kc], bh0[nt], bh1[nt]);
            }
        }

        // exp + repack C-frag -> A-frag (P hi/lo)
        uint32_t ph[2][4], pl[2][4];
        #pragma unroll
        for (int nt = 0; nt < 4; nt++) {
            float p0 = __expf(sacc[nt][0] - mii0);
            float p1 = __expf(sacc[nt][1] - mii0);
            float p2 = __expf(sacc[nt][2] - mii1);
            float p3 = __expf(sacc[nt][3] - mii1);
            den0 += p0 + p1;
            den1 += p2 + p3;
            uint32_t h01, l01, h23, l23;
            split2(p0, p1, h01, l01);
            split2(p2, p3, h23, l23);
            int kc2 = nt >> 1;
            if ((nt & 1) == 0) {
                ph[kc2][0] = h01; ph[kc2][1] = h23;
                pl[kc2][0] = l01; pl[kc2][1] = l23;
            } else {
                ph[kc2][2] = h01; ph[kc2][3] = h23;
                pl[kc2][2] = l01; pl[kc2][3] = l23;
            }
        }

        // acc += P . X^T
        #pragma unroll
        for (int kc2 = 0; kc2 < 2; kc2++) {
            uint32_t h0[8], h1[8], l0[8], l1[8];
            ldm4(&h0[0], bXh + kc2 * 32);
            ldm4(&h0[4], bXh + 2560 + kc2 * 32);
            ldm4(&h1[0], bXh + kc2 * 32 + 16);
            ldm4(&h1[4], bXh + 2560 + kc2 * 32 + 16);
            ldm4(&l0[0], bXl + kc2 * 32);
            ldm4(&l0[4], bXl + 2560 + kc2 * 32);
            ldm4(&l1[0], bXl + kc2 * 32 + 16);
            ldm4(&l1[4], bXl + 2560 + kc2 * 32 + 16);
            #pragma unroll
            for (int dt = 0; dt < 8; dt++) {
                mma16816(acc[dt], ph[kc2], h0[dt], h1[dt]);
                mma16816(acc[dt], ph[kc2], l0[dt], l1[dt]);
                mma16816(acc[dt], pl[kc2], h0[dt], h1[dt]);
            }
        }
        __syncthreads();
    }

    den0 += __shfl_xor_sync(~0u, den0, 1);
    den0 += __shfl_xor_sync(~0u, den0, 2);
    den1 += __shfl_xor_sync(~0u, den1, 1);
    den1 += __shfl_xor_sync(~0u, den1, 2);

    float* pa = g_pacc[kh];
    #pragma unroll
    for (int dt = 0; dt < 8; dt++) {
        *(float2*)(pa + qrow * 64 + dt * 8 + 2 * tig) =
            make_float2(acc[dt][0], acc[dt][1]);
        *(float2*)(pa + (qrow + 8) * 64 + dt * 8 + 2 * tig) =
            make_float2(acc[dt][2], acc[dt][3]);
    }
    if (tig == 0) {   // lane 4*gr holds row gr's reduced denominator
        g_pden[kh][qrow]     = den0;
        g_pden[kh][qrow + 8] = den1;
    }
}

// ---------------- K3: W = node_emb @ wpool via HMMA (R8 scalar version) -----
__global__ __launch_bounds__(256) void k_wgemm_mma()
{
    __shared__ uint32_t sBh[128][36], sBl[128][36];
    const int tid = threadIdx.x, w = tid >> 5, l = tid & 31;
    const int gr = l >> 2, tig = l & 3;
    const int n0 = blockIdx.y * 128, c0 = blockIdx.x * 128;

    for (int i = tid; i < 4096; i += 256) {
        int c = i >> 5, dp = i & 31;
        sBh[c][dp] = g_Bph[(size_t)(c0 + c) * 32 + dp];
        sBl[c][dp] = g_Bpl[(size_t)(c0 + c) * 32 + dp];
    }

    const size_t ar = (size_t)(n0 + w * 16 + gr);
    uint32_t Ahf[4][4], Alf[4][4];
    #pragma unroll
    for (int kc = 0; kc < 4; kc++) {
        int p0 = kc * 8 + tig, p1 = kc * 8 + 4 + tig;
        Ahf[kc][0] = g_Ah[ar * 32 + p0];
        Ahf[kc][1] = g_Ah[(ar + 8) * 32 + p0];
        Ahf[kc][2] = g_Ah[ar * 32 + p1];
        Ahf[kc][3] = g_Ah[(ar + 8) * 32 + p1];
        Alf[kc][0] = g_Al[ar * 32 + p0];
        Alf[kc][1] = g_Al[(ar + 8) * 32 + p0];
        Alf[kc][2] = g_Al[ar * 32 + p1];
        Alf[kc][3] = g_Al[(ar + 8) * 32 + p1];
    }
    __syncthreads();

    float acc[16][4];
    #pragma unroll
    for (int i = 0; i < 16; i++)
        #pragma unroll
        for (int j = 0; j < 4; j++) acc[i][j] = 0.f;

    #pragma unroll
    for (int ct = 0; ct < 16; ct++) {
        const uint32_t* bh = sBh[ct * 8 + gr];
        const uint32_t* bl = sBl[ct * 8 + gr];
        #pragma unroll
        for (int kc = 0; kc < 4; kc++) {
            uint32_t bh0 = bh[kc * 8 + tig], bh1 = bh[kc * 8 + 4 + tig];
            uint32_t bl0 = bl[kc * 8 + tig], bl1 = bl[kc * 8 + 4 + tig];
            mma16816(acc[ct], Ahf[kc], bh0, bh1);
            mma16816(acc[ct], Ahf[kc], bl0, bl1);
            mma16816(acc[ct], Alf[kc], bh0, bh1);
        }
    }

    #pragma unroll
    for (int ct = 0; ct < 16; ct++) {
        float* p = g_W + ar * WC + c0 + ct * 8 + 2 * tig;
        *(float2*)p            = make_float2(acc[ct][0], acc[ct][1]);
        *(float2*)(p + 8 * WC) = make_float2(acc[ct][2], acc[ct][3]);
    }
}

// ---------------- K5: combine partials + apply hypernet weights ------------
__global__ __launch_bounds__(384) void k_apply(const float* __restrict__ x,
                                               float* __restrict__ out)
{
    __shared__ float Ws[WC];
    __shared__ float xs[BT * DD];
    __shared__ float x2s[BT * DD];
    int n = blockIdx.x;
    const float4* Wn = (const float4*)(g_W + (size_t)n * WC);
    for (int i = threadIdx.x; i < WC / 4; i += 384) ((float4*)Ws)[i] = Wn[i];
    for (int i = threadIdx.x; i < BT * 16; i += 384) {
        int bt = i >> 4, c4 = i & 15;
        size_t base = ((size_t)bt * NN + n) * DD;
        ((float4*)xs)[i] = ((const float4*)(x + base))[c4];
        float inv = 1.f / (g_pden[0][bt * NN + n] + g_pden[1][bt * NN + n]);
        float4 a = ((const float4*)(g_pacc[0] + base))[c4];
        float4 b = ((const float4*)(g_pacc[1] + base))[c4];
        ((float4*)x2s)[i] = make_float4((a.x + b.x) * inv, (a.y + b.y) * inv,
                                        (a.z + b.z) * inv, (a.w + b.w) * inv);
    }
    __syncthreads();
    int bt = threadIdx.x / 64, o = threadIdx.x & 63;
    float s = g_bias[bt * DD + o];
    #pragma unroll
    for (int i = 0; i < DD; i++) s += xs[bt * DD + i] * Ws[i * DD + o];
    #pragma unroll
    for (int i = 0; i < DD; i++) s += x2s[bt * DD + i] * Ws[4096 + i * DD + o];
    out[((size_t)bt * NN + n) * DD + o] = s;
}

// ---------------------------------------------------------------------------
extern "C" void kernel_launch(void* const* d_in, const int* in_sizes, int n_in,
                              void* d_out, int out_size)
{
    const float* x     = (const float*)d_in[0];
    const float* ne    = (const float*)d_in[1];
    const float* te    = (const float*)d_in[2];
    const float* wpool = (const float*)d_in[3];
    const float* bpool = (const float*)d_in[4];
    const float* gamma = (const float*)d_in[5];
    const float* beta  = (const float*)d_in[6];
    float* out = (float*)d_out;

    // k_attn_mma placed 4th so the ncu capture (launch #4) profiles it.
    k_ln       <<<(BT * NN) / 8, 256>>>(ne, te, gamma, beta);
    k_xsplit   <<<dim3(NN / 64, BT), 256>>>(x);
    k_wpsplit  <<<WC / 32, 256>>>(wpool, te, bpool);
    k_attn_mma <<<dim3(NN / 128, BT, 2), 256>>>();
    k_wgemm_mma<<<dim3(WC / 128, NN / 128), 256>>>();
    k_apply    <<<NN, 384>>>(x, out);
}

// round 14
// speedup vs baseline: 1.0122x; 1.0122x over previous
#include <cuda_runtime.h>
#include <cuda_bf16.h>
#include <cstdint>

#define BT 6
#define NN 4096
#define DD 64
#define WC 8192

typedef unsigned long long u64;

// Scratch (device globals — no allocations allowed)
__device__ float    g_mii [BT*NN];
__device__ uint32_t g_Eh32[BT*NN*32];        // E hi (bf16x2 along d)
__device__ uint32_t g_El32[BT*NN*32];        // E lo
__device__ uint32_t g_Xth [BT*DD*(NN/2)];    // X^T hi: [bt*64+d][k/2]
__device__ uint32_t g_Xtl [BT*DD*(NN/2)];    // X^T lo
__device__ uint32_t g_Ah  [NN*32];           // node_emb hi (bf16x2 along d)
__device__ uint32_t g_Al  [NN*32];           // node_emb lo
__device__ uint32_t g_Bph [WC*32];           // wpool^T hi: [c][d/2]
__device__ uint32_t g_Bpl [WC*32];           // wpool^T lo
__device__ float    g_W   [(size_t)NN*WC];   // hypernet weights, 134 MB
__device__ float    g_pacc[2][BT*NN*DD];     // attention partial numerators
__device__ float    g_pden[2][BT*NN];        // attention partial denominators
__device__ float    g_bias[BT*DD];

// ---------------- helpers ----------------
__device__ __forceinline__ uint32_t pkbf(float a, float b) {
    __nv_bfloat162 t; t.x = __float2bfloat16(a); t.y = __float2bfloat16(b);
    return *reinterpret_cast<uint32_t*>(&t);
}
__device__ __forceinline__ void split2(float a, float b, uint32_t& hi, uint32_t& lo) {
    __nv_bfloat16 ha = __float2bfloat16(a), hb = __float2bfloat16(b);
    __nv_bfloat162 hp; hp.x = ha; hp.y = hb;
    hi = *reinterpret_cast<uint32_t*>(&hp);
    lo = pkbf(a - __bfloat162float(ha), b - __bfloat162float(hb));
}
__device__ __forceinline__ void mma16816(float* c, const uint32_t* a, uint32_t b0, uint32_t b1) {
    asm volatile(
        "mma.sync.aligned.m16n8k16.row.col.f32.bf16.bf16.f32 "
        "{%0,%1,%2,%3}, {%4,%5,%6,%7}, {%8,%9}, {%0,%1,%2,%3};"
        : "+f"(c[0]), "+f"(c[1]), "+f"(c[2]), "+f"(c[3])
        : "r"(a[0]), "r"(a[1]), "r"(a[2]), "r"(a[3]), "r"(b0), "r"(b1));
}
// load 4 8x8 b16 matrices; lane l supplies row (l&7) addr of matrix (l>>3)
__device__ __forceinline__ void ldm4(uint32_t* r, uint32_t saddr) {
    asm volatile("ldmatrix.sync.aligned.m8n8.x4.shared.b16 {%0,%1,%2,%3}, [%4];"
        : "=r"(r[0]), "=r"(r[1]), "=r"(r[2]), "=r"(r[3]) : "r"(saddr));
}
__device__ __forceinline__ uint32_t s2u(const void* p) {
    return (uint32_t)__cvta_generic_to_shared(p);
}
__device__ __forceinline__ void cpa16(void* dst, const void* src) {
    uint32_t d = (uint32_t)__cvta_generic_to_shared(dst);
    asm volatile("cp.async.ca.shared.global [%0], [%1], 16;" :: "r"(d), "l"(src));
}
#define CP_COMMIT() asm volatile("cp.async.commit_group;" ::: "memory")
#define CP_WAIT1()  asm volatile("cp.async.wait_group 1;" ::: "memory")

// ---------------- K1: LayerNorm -> bf16 hi/lo + mii (+node_emb split) ------
__global__ __launch_bounds__(256) void k_ln(
    const float* __restrict__ ne, const float* __restrict__ te,
    const float* __restrict__ gamma, const float* __restrict__ beta)
{
    int row = blockIdx.x * 8 + (threadIdx.x >> 5);
    int lane = threadIdx.x & 31;
    int bt = row >> 12, n = row & (NN - 1);
    float2 nv = *(const float2*)(ne + n * DD + 2 * lane);
    float2 tv = *(const float2*)(te + bt * DD + 2 * lane);

    if (bt == 0) {
        uint32_t hi, lo;
        split2(nv.x, nv.y, hi, lo);
        g_Ah[n * 32 + lane] = hi;
        g_Al[n * 32 + lane] = lo;
    }

    float e0 = nv.x + tv.x, e1 = nv.y + tv.y;
    float s = e0 + e1, s2 = e0 * e0 + e1 * e1;
    #pragma unroll
    for (int o = 16; o; o >>= 1) {
        s  += __shfl_xor_sync(~0u, s,  o);
        s2 += __shfl_xor_sync(~0u, s2, o);
    }
    float mu = s * (1.f / 64.f), var = s2 * (1.f / 64.f) - mu * mu;
    float rs = rsqrtf(var + 1e-12f);
    float o0 = (e0 - mu) * rs * gamma[2 * lane]     + beta[2 * lane];
    float o1 = (e1 - mu) * rs * gamma[2 * lane + 1] + beta[2 * lane + 1];
    uint32_t hi, lo;
    split2(o0, o1, hi, lo);
    g_Eh32[row * 32 + lane] = hi;
    g_El32[row * 32 + lane] = lo;
    float q2 = o0 * o0 + o1 * o1;
    #pragma unroll
    for (int o = 16; o; o >>= 1) q2 += __shfl_xor_sync(~0u, q2, o);
    if (lane == 0) g_mii[row] = q2;
}

// ---------------- K1b: X -> X^T bf16 hi/lo ----------------
__global__ __launch_bounds__(256) void k_xsplit(const float* __restrict__ x)
{
    __shared__ float t[64][65];
    int bt = blockIdx.y, k0 = blockIdx.x * 64;
    for (int i = threadIdx.x; i < 4096; i += 256)
        t[i >> 6][i & 63] = x[((size_t)bt * NN + k0 + (i >> 6)) * DD + (i & 63)];
    __syncthreads();
    for (int i = threadIdx.x; i < 2048; i += 256) {
        int d = i >> 5, c2 = i & 31;
        uint32_t hi, lo;
        split2(t[c2 * 2][d], t[c2 * 2 + 1][d], hi, lo);
        size_t gi = (size_t)(bt * DD + d) * (NN / 2) + k0 / 2 + c2;
        g_Xth[gi] = hi;
        g_Xtl[gi] = lo;
    }
}

// ---------------- K1d: wpool -> transposed bf16 hi/lo [c][d/2]  (+bias) -----
__global__ __launch_bounds__(256) void k_wpsplit(
    const float* __restrict__ wp, const float* __restrict__ te,
    const float* __restrict__ bp)
{
    __shared__ float t[64][33];
    int c0 = blockIdx.x * 32;
    for (int i = threadIdx.x; i < 2048; i += 256)
        t[i >> 5][i & 31] = wp[(size_t)(i >> 5) * WC + c0 + (i & 31)];
    __syncthreads();
    for (int i = threadIdx.x; i < 1024; i += 256) {
        int c = i >> 5, dp = i & 31;
        uint32_t hi, lo;
        split2(t[dp * 2][c], t[dp * 2 + 1][c], hi, lo);
        g_Bph[(size_t)(c0 + c) * 32 + dp] = hi;
        g_Bpl[(size_t)(c0 + c) * 32 + dp] = lo;
    }
    if (blockIdx.x == 0) {   // folded bias: bias[bt,o] = te[bt,:].bp[:,o]
        for (int i = threadIdx.x; i < BT * DD; i += 256) {
            int bt = i >> 6, o = i & 63;
            float s = 0.f;
            #pragma unroll
            for (int d = 0; d < DD; d++) s += te[bt * DD + d] * bp[d * DD + o];
            g_bias[i] = s;
        }
    }
}

// ---------------- K4: HMMA attention, 256 thr / 128 q, 2 blocks/SM ---------
__global__ __launch_bounds__(256, 2) void k_attn_mma()
{
    __shared__ __align__(16) uint32_t sEh[2][32][36], sEl[2][32][36];
    __shared__ __align__(16) uint32_t sXh[2][64][20], sXl[2][64][20];

    const int tid = threadIdx.x, w = tid >> 5, l = tid & 31;
    const int tig = l & 3, gr = l >> 2;
    const int bt = blockIdx.y;
    const int q0 = blockIdx.x * 128;
    const int kh = blockIdx.z;
    const int k0 = kh * (NN / 2);

    const size_t qrow = (size_t)(bt * NN + q0 + w * 16 + gr);
    uint32_t Qh[4][4], Ql[4][4];
    #pragma unroll
    for (int kc = 0; kc < 4; kc++) {
        int c0 = kc * 8 + tig, c1 = kc * 8 + 4 + tig;
        Qh[kc][0] = g_Eh32[qrow * 32 + c0];
        Qh[kc][1] = g_Eh32[(qrow + 8) * 32 + c0];
        Qh[kc][2] = g_Eh32[qrow * 32 + c1];
        Qh[kc][3] = g_Eh32[(qrow + 8) * 32 + c1];
        Ql[kc][0] = g_El32[qrow * 32 + c0];
        Ql[kc][1] = g_El32[(qrow + 8) * 32 + c0];
        Ql[kc][2] = g_El32[qrow * 32 + c1];
        Ql[kc][3] = g_El32[(qrow + 8) * 32 + c1];
    }
    const float mii0 = g_mii[qrow];
    const float mii1 = g_mii[qrow + 8];

    const uint32_t aEh = s2u(&sEh[0][l][0]);   // + b*4608
    const uint32_t aEl = s2u(&sEl[0][l][0]);
    const uint32_t aXh = s2u(&sXh[0][l][0]);   // + b*5120 (+2560 for dg=1)
    const uint32_t aXl = s2u(&sXl[0][l][0]);

    float acc[8][4];
    #pragma unroll
    for (int i = 0; i < 8; i++)
        #pragma unroll
        for (int j = 0; j < 4; j++) acc[i][j] = 0.f;
    float den0 = 0.f, den1 = 0.f;

    auto prefetch = [&](int t) {
        if (t < 64) {
            int b = t & 1, m = k0 + t * 32;
            {
                int i = tid;                     // E tiles: 32 rows x 8 chunks
                int r = i >> 3, c = (i & 7) << 2;
                size_t g = (size_t)(bt * NN + m + r) * 32 + c;
                cpa16(&sEh[b][r][c], g_Eh32 + g);
                cpa16(&sEl[b][r][c], g_El32 + g);
            }
            {
                int i = tid;                     // X tiles: 64 rows x 4 chunks
                int r = i >> 2, c = (i & 3) << 2;
                size_t g = (size_t)(bt * DD + r) * (NN / 2) + (m >> 1) + c;
                cpa16(&sXh[b][r][c], g_Xth + g);
                cpa16(&sXl[b][r][c], g_Xtl + g);
            }
        }
        CP_COMMIT();
    };

    prefetch(0);

    for (int t = 0; t < 64; t++) {
        prefetch(t + 1);
        CP_WAIT1();
        __syncthreads();

        const uint32_t bEh = aEh + (t & 1) * 4608;
        const uint32_t bEl = aEl + (t & 1) * 4608;
        const uint32_t bXh = aXh + (t & 1) * 5120;
        const uint32_t bXl = aXl + (t & 1) * 5120;

        // S = Eq . Ek^T
        float sacc[4][4];
        #pragma unroll
        for (int i = 0; i < 4; i++)
            #pragma unroll
            for (int j = 0; j < 4; j++) sacc[i][j] = 0.f;
        #pragma unroll
        for (int kc = 0; kc < 4; kc++) {
            uint32_t bh0[4], bh1[4], bl0[4], bl1[4];
            ldm4(bh0, bEh + kc * 32);
            ldm4(bh1, bEh + kc * 32 + 16);
            ldm4(bl0, bEl + kc * 32);
            ldm4(bl1, bEl + kc * 32 + 16);
            #pragma unroll
            for (int nt = 0; nt < 4; nt++) {
                mma16816(sacc[nt], Qh[kc], bh0[nt], bh1[nt]);
                mma16816(sacc[nt], Qh[kc], bl0[nt], bl1[nt]);
                mma16816(sacc[nt], Ql[kc], bh0[nt], bh1[nt]);
            }
        }

        // exp + repack C-frag -> A-frag (P hi/lo)
        uint32_t ph[2][4], pl[2][4];
        #pragma unroll
        for (int nt = 0; nt < 4; nt++) {
            float p0 = __expf(sacc[nt][0] - mii0);
            float p1 = __expf(sacc[nt][1] - mii0);
            float p2 = __expf(sacc[nt][2] - mii1);
            float p3 = __expf(sacc[nt][3] - mii1);
            den0 += p0 + p1;
            den1 += p2 + p3;
            uint32_t h01, l01, h23, l23;
            split2(p0, p1, h01, l01);
            split2(p2, p3, h23, l23);
            int kc2 = nt >> 1;
            if ((nt & 1) == 0) {
                ph[kc2][0] = h01; ph[kc2][1] = h23;
                pl[kc2][0] = l01; pl[kc2][1] = l23;
            } else {
                ph[kc2][2] = h01; ph[kc2][3] = h23;
                pl[kc2][2] = l01; pl[kc2][3] = l23;
            }
        }

        // acc += P . X^T  (4-tile d-groups to cap register temporaries)
        #pragma unroll
        for (int kc2 = 0; kc2 < 2; kc2++) {
            #pragma unroll
            for (int dg = 0; dg < 2; dg++) {
                uint32_t h0[4], h1[4], l0[4], l1[4];
                ldm4(h0, bXh + dg * 2560 + kc2 * 32);
                ldm4(h1, bXh + dg * 2560 + kc2 * 32 + 16);
                ldm4(l0, bXl + dg * 2560 + kc2 * 32);
                ldm4(l1, bXl + dg * 2560 + kc2 * 32 + 16);
                #pragma unroll
                for (int i = 0; i < 4; i++) {
                    int dt = dg * 4 + i;
                    mma16816(acc[dt], ph[kc2], h0[i], h1[i]);
                    mma16816(acc[dt], ph[kc2], l0[i], l1[i]);
                    mma16816(acc[dt], pl[kc2], h0[i], h1[i]);
                }
            }
        }
        __syncthreads();
    }

    den0 += __shfl_xor_sync(~0u, den0, 1);
    den0 += __shfl_xor_sync(~0u, den0, 2);
    den1 += __shfl_xor_sync(~0u, den1, 1);
    den1 += __shfl_xor_sync(~0u, den1, 2);

    float* pa = g_pacc[kh];
    #pragma unroll
    for (int dt = 0; dt < 8; dt++) {
        *(float2*)(pa + qrow * 64 + dt * 8 + 2 * tig) =
            make_float2(acc[dt][0], acc[dt][1]);
        *(float2*)(pa + (qrow + 8) * 64 + dt * 8 + 2 * tig) =
            make_float2(acc[dt][2], acc[dt][3]);
    }
    if (tig == 0) {   // lane 4*gr holds row gr's reduced denominator
        g_pden[kh][qrow]     = den0;
        g_pden[kh][qrow + 8] = den1;
    }
}

// ---------------- K3: W = node_emb @ wpool via HMMA (R8 scalar version) -----
__global__ __launch_bounds__(256) void k_wgemm_mma()
{
    __shared__ uint32_t sBh[128][36], sBl[128][36];
    const int tid = threadIdx.x, w = tid >> 5, l = tid & 31;
    const int gr = l >> 2, tig = l & 3;
    const int n0 = blockIdx.y * 128, c0 = blockIdx.x * 128;

    for (int i = tid; i < 4096; i += 256) {
        int c = i >> 5, dp = i & 31;
        sBh[c][dp] = g_Bph[(size_t)(c0 + c) * 32 + dp];
        sBl[c][dp] = g_Bpl[(size_t)(c0 + c) * 32 + dp];
    }

    const size_t ar = (size_t)(n0 + w * 16 + gr);
    uint32_t Ahf[4][4], Alf[4][4];
    #pragma unroll
    for (int kc = 0; kc < 4; kc++) {
        int p0 = kc * 8 + tig, p1 = kc * 8 + 4 + tig;
        Ahf[kc][0] = g_Ah[ar * 32 + p0];
        Ahf[kc][1] = g_Ah[(ar + 8) * 32 + p0];
        Ahf[kc][2] = g_Ah[ar * 32 + p1];
        Ahf[kc][3] = g_Ah[(ar + 8) * 32 + p1];
        Alf[kc][0] = g_Al[ar * 32 + p0];
        Alf[kc][1] = g_Al[(ar + 8) * 32 + p0];
        Alf[kc][2] = g_Al[ar * 32 + p1];
        Alf[kc][3] = g_Al[(ar + 8) * 32 + p1];
    }
    __syncthreads();

    float acc[16][4];
    #pragma unroll
    for (int i = 0; i < 16; i++)
        #pragma unroll
        for (int j = 0; j < 4; j++) acc[i][j] = 0.f;

    #pragma unroll
    for (int ct = 0; ct < 16; ct++) {
        const uint32_t* bh = sBh[ct * 8 + gr];
        const uint32_t* bl = sBl[ct * 8 + gr];
        #pragma unroll
        for (int kc = 0; kc < 4; kc++) {
            uint32_t bh0 = bh[kc * 8 + tig], bh1 = bh[kc * 8 + 4 + tig];
            uint32_t bl0 = bl[kc * 8 + tig], bl1 = bl[kc * 8 + 4 + tig];
            mma16816(acc[ct], Ahf[kc], bh0, bh1);
            mma16816(acc[ct], Ahf[kc], bl0, bl1);
            mma16816(acc[ct], Alf[kc], bh0, bh1);
        }
    }

    #pragma unroll
    for (int ct = 0; ct < 16; ct++) {
        float* p = g_W + ar * WC + c0 + ct * 8 + 2 * tig;
        *(float2*)p            = make_float2(acc[ct][0], acc[ct][1]);
        *(float2*)(p + 8 * WC) = make_float2(acc[ct][2], acc[ct][3]);
    }
}

// ---------------- K5: combine partials + apply hypernet weights ------------
__global__ __launch_bounds__(384) void k_apply(const float* __restrict__ x,
                                               float* __restrict__ out)
{
    __shared__ float Ws[WC];
    __shared__ float xs[BT * DD];
    __shared__ float x2s[BT * DD];
    int n = blockIdx.x;
    const float4* Wn = (const float4*)(g_W + (size_t)n * WC);
    for (int i = threadIdx.x; i < WC / 4; i += 384) ((float4*)Ws)[i] = Wn[i];
    for (int i = threadIdx.x; i < BT * 16; i += 384) {
        int bt = i >> 4, c4 = i & 15;
        size_t base = ((size_t)bt * NN + n) * DD;
        ((float4*)xs)[i] = ((const float4*)(x + base))[c4];
        float inv = 1.f / (g_pden[0][bt * NN + n] + g_pden[1][bt * NN + n]);
        float4 a = ((const float4*)(g_pacc[0] + base))[c4];
        float4 b = ((const float4*)(g_pacc[1] + base))[c4];
        ((float4*)x2s)[i] = make_float4((a.x + b.x) * inv, (a.y + b.y) * inv,
                                        (a.z + b.z) * inv, (a.w + b.w) * inv);
    }
    __syncthreads();
    int bt = threadIdx.x / 64, o = threadIdx.x & 63;
    float s = g_bias[bt * DD + o];
    #pragma unroll
    for (int i = 0; i < DD; i++) s += xs[bt * DD + i] * Ws[i * DD + o];
    #pragma unroll
    for (int i = 0; i < DD; i++) s += x2s[bt * DD + i] * Ws[4096 + i * DD + o];
    out[((size_t)bt * NN + n) * DD + o] = s;
}

// ---------------------------------------------------------------------------
extern "C" void kernel_launch(void* const* d_in, const int* in_sizes, int n_in,
                              void* d_out, int out_size)
{
    const float* x     = (const float*)d_in[0];
    const float* ne    = (const float*)d_in[1];
    const float* te    = (const float*)d_in[2];
    const float* wpool = (const float*)d_in[3];
    const float* bpool = (const float*)d_in[4];
    const float* gamma = (const float*)d_in[5];
    const float* beta  = (const float*)d_in[6];
    float* out = (float*)d_out;

    // k_attn_mma placed 4th so the ncu capture (launch #4) profiles it.
    k_ln       <<<(BT * NN) / 8, 256>>>(ne, te, gamma, beta);
    k_xsplit   <<<dim3(NN / 64, BT), 256>>>(x);
    k_wpsplit  <<<WC / 32, 256>>>(wpool, te, bpool);
    k_attn_mma <<<dim3(NN / 128, BT, 2), 256>>>();
    k_wgemm_mma<<<dim3(WC / 128, NN / 128), 256>>>();
    k_apply    <<<NN, 384>>>(x, out);
}

// round 15
// speedup vs baseline: 1.0656x; 1.0527x over previous
#include <cuda_runtime.h>
#include <cuda_bf16.h>
#include <cstdint>

#define BT 6
#define NN 4096
#define DD 64
#define WC 8192
#define KSPLIT 4

typedef unsigned long long u64;

// Scratch (device globals — no allocations allowed)
__device__ float    g_mii [BT*NN];
__device__ uint32_t g_Eh32[BT*NN*32];        // E hi (bf16x2 along d)
__device__ uint32_t g_El32[BT*NN*32];        // E lo
__device__ uint32_t g_Xth [BT*DD*(NN/2)];    // X^T hi: [bt*64+d][k/2]
__device__ uint32_t g_Xtl [BT*DD*(NN/2)];    // X^T lo
__device__ uint32_t g_Ah  [NN*32];           // node_emb hi (bf16x2 along d)
__device__ uint32_t g_Al  [NN*32];           // node_emb lo
__device__ uint32_t g_Bph [WC*32];           // wpool^T hi: [c][d/2]
__device__ uint32_t g_Bpl [WC*32];           // wpool^T lo
__device__ float    g_W   [(size_t)NN*WC];   // hypernet weights, 134 MB
__device__ float    g_pacc[KSPLIT][BT*NN*DD];// attention partial numerators
__device__ float    g_pden[KSPLIT][BT*NN];   // attention partial denominators
__device__ float    g_bias[BT*DD];

// ---------------- helpers ----------------
__device__ __forceinline__ uint32_t pkbf(float a, float b) {
    __nv_bfloat162 t; t.x = __float2bfloat16(a); t.y = __float2bfloat16(b);
    return *reinterpret_cast<uint32_t*>(&t);
}
__device__ __forceinline__ void split2(float a, float b, uint32_t& hi, uint32_t& lo) {
    __nv_bfloat16 ha = __float2bfloat16(a), hb = __float2bfloat16(b);
    __nv_bfloat162 hp; hp.x = ha; hp.y = hb;
    hi = *reinterpret_cast<uint32_t*>(&hp);
    lo = pkbf(a - __bfloat162float(ha), b - __bfloat162float(hb));
}
__device__ __forceinline__ void mma16816(float* c, const uint32_t* a, uint32_t b0, uint32_t b1) {
    asm volatile(
        "mma.sync.aligned.m16n8k16.row.col.f32.bf16.bf16.f32 "
        "{%0,%1,%2,%3}, {%4,%5,%6,%7}, {%8,%9}, {%0,%1,%2,%3};"
        : "+f"(c[0]), "+f"(c[1]), "+f"(c[2]), "+f"(c[3])
        : "r"(a[0]), "r"(a[1]), "r"(a[2]), "r"(a[3]), "r"(b0), "r"(b1));
}
// load 4 8x8 b16 matrices; lane l supplies row (l&7) addr of matrix (l>>3)
__device__ __forceinline__ void ldm4(uint32_t* r, uint32_t saddr) {
    asm volatile("ldmatrix.sync.aligned.m8n8.x4.shared.b16 {%0,%1,%2,%3}, [%4];"
        : "=r"(r[0]), "=r"(r[1]), "=r"(r[2]), "=r"(r[3]) : "r"(saddr));
}
__device__ __forceinline__ uint32_t s2u(const void* p) {
    return (uint32_t)__cvta_generic_to_shared(p);
}
__device__ __forceinline__ void cpa16(void* dst, const void* src) {
    uint32_t d = (uint32_t)__cvta_generic_to_shared(dst);
    asm volatile("cp.async.ca.shared.global [%0], [%1], 16;" :: "r"(d), "l"(src));
}
#define CP_COMMIT() asm volatile("cp.async.commit_group;" ::: "memory")
#define CP_WAIT1()  asm volatile("cp.async.wait_group 1;" ::: "memory")

// ---------------- K1: LayerNorm -> bf16 hi/lo + mii (+node_emb split) ------
__global__ __launch_bounds__(256) void k_ln(
    const float* __restrict__ ne, const float* __restrict__ te,
    const float* __restrict__ gamma, const float* __restrict__ beta)
{
    int row = blockIdx.x * 8 + (threadIdx.x >> 5);
    int lane = threadIdx.x & 31;
    int bt = row >> 12, n = row & (NN - 1);
    float2 nv = *(const float2*)(ne + n * DD + 2 * lane);
    float2 tv = *(const float2*)(te + bt * DD + 2 * lane);

    if (bt == 0) {
        uint32_t hi, lo;
        split2(nv.x, nv.y, hi, lo);
        g_Ah[n * 32 + lane] = hi;
        g_Al[n * 32 + lane] = lo;
    }

    float e0 = nv.x + tv.x, e1 = nv.y + tv.y;
    float s = e0 + e1, s2 = e0 * e0 + e1 * e1;
    #pragma unroll
    for (int o = 16; o; o >>= 1) {
        s  += __shfl_xor_sync(~0u, s,  o);
        s2 += __shfl_xor_sync(~0u, s2, o);
    }
    float mu = s * (1.f / 64.f), var = s2 * (1.f / 64.f) - mu * mu;
    float rs = rsqrtf(var + 1e-12f);
    float o0 = (e0 - mu) * rs * gamma[2 * lane]     + beta[2 * lane];
    float o1 = (e1 - mu) * rs * gamma[2 * lane + 1] + beta[2 * lane + 1];
    uint32_t hi, lo;
    split2(o0, o1, hi, lo);
    g_Eh32[row * 32 + lane] = hi;
    g_El32[row * 32 + lane] = lo;
    float q2 = o0 * o0 + o1 * o1;
    #pragma unroll
    for (int o = 16; o; o >>= 1) q2 += __shfl_xor_sync(~0u, q2, o);
    if (lane == 0) g_mii[row] = q2;
}

// ---------------- K1b: X -> X^T bf16 hi/lo ----------------
__global__ __launch_bounds__(256) void k_xsplit(const float* __restrict__ x)
{
    __shared__ float t[64][65];
    int bt = blockIdx.y, k0 = blockIdx.x * 64;
    for (int i = threadIdx.x; i < 4096; i += 256)
        t[i >> 6][i & 63] = x[((size_t)bt * NN + k0 + (i >> 6)) * DD + (i & 63)];
    __syncthreads();
    for (int i = threadIdx.x; i < 2048; i += 256) {
        int d = i >> 5, c2 = i & 31;
        uint32_t hi, lo;
        split2(t[c2 * 2][d], t[c2 * 2 + 1][d], hi, lo);
        size_t gi = (size_t)(bt * DD + d) * (NN / 2) + k0 / 2 + c2;
        g_Xth[gi] = hi;
        g_Xtl[gi] = lo;
    }
}

// ---------------- K1d: wpool -> transposed bf16 hi/lo [c][d/2]  (+bias) -----
__global__ __launch_bounds__(256) void k_wpsplit(
    const float* __restrict__ wp, const float* __restrict__ te,
    const float* __restrict__ bp)
{
    __shared__ float t[64][33];
    int c0 = blockIdx.x * 32;
    for (int i = threadIdx.x; i < 2048; i += 256)
        t[i >> 5][i & 31] = wp[(size_t)(i >> 5) * WC + c0 + (i & 31)];
    __syncthreads();
    for (int i = threadIdx.x; i < 1024; i += 256) {
        int c = i >> 5, dp = i & 31;
        uint32_t hi, lo;
        split2(t[dp * 2][c], t[dp * 2 + 1][c], hi, lo);
        g_Bph[(size_t)(c0 + c) * 32 + dp] = hi;
        g_Bpl[(size_t)(c0 + c) * 32 + dp] = lo;
    }
    if (blockIdx.x == 0) {   // folded bias: bias[bt,o] = te[bt,:].bp[:,o]
        for (int i = threadIdx.x; i < BT * DD; i += 256) {
            int bt = i >> 6, o = i & 63;
            float s = 0.f;
            #pragma unroll
            for (int d = 0; d < DD; d++) s += te[bt * DD + d] * bp[d * DD + o];
            g_bias[i] = s;
        }
    }
}

// ---------------- K4: HMMA attention, 128 thr / 64 q, 4-way key split ------
__global__ __launch_bounds__(128, 4) void k_attn_mma()
{
    __shared__ __align__(16) uint32_t sEh[2][32][36], sEl[2][32][36];
    __shared__ __align__(16) uint32_t sXh[2][64][20], sXl[2][64][20];

    const int tid = threadIdx.x, w = tid >> 5, l = tid & 31;
    const int tig = l & 3, gr = l >> 2;
    const int bt = blockIdx.y;
    const int q0 = blockIdx.x * 64;
    const int kh = blockIdx.z;
    const int k0 = kh * (NN / KSPLIT);

    const size_t qrow = (size_t)(bt * NN + q0 + w * 16 + gr);
    uint32_t Qh[4][4], Ql[4][4];
    #pragma unroll
    for (int kc = 0; kc < 4; kc++) {
        int c0 = kc * 8 + tig, c1 = kc * 8 + 4 + tig;
        Qh[kc][0] = g_Eh32[qrow * 32 + c0];
        Qh[kc][1] = g_Eh32[(qrow + 8) * 32 + c0];
        Qh[kc][2] = g_Eh32[qrow * 32 + c1];
        Qh[kc][3] = g_Eh32[(qrow + 8) * 32 + c1];
        Ql[kc][0] = g_El32[qrow * 32 + c0];
        Ql[kc][1] = g_El32[(qrow + 8) * 32 + c0];
        Ql[kc][2] = g_El32[qrow * 32 + c1];
        Ql[kc][3] = g_El32[(qrow + 8) * 32 + c1];
    }
    const float mii0 = g_mii[qrow];
    const float mii1 = g_mii[qrow + 8];

    const uint32_t aEh = s2u(&sEh[0][l][0]);   // + b*4608
    const uint32_t aEl = s2u(&sEl[0][l][0]);
    const uint32_t aXh = s2u(&sXh[0][l][0]);   // + b*5120 (+2560 for dg=1)
    const uint32_t aXl = s2u(&sXl[0][l][0]);

    float acc[8][4];
    #pragma unroll
    for (int i = 0; i < 8; i++)
        #pragma unroll
        for (int j = 0; j < 4; j++) acc[i][j] = 0.f;
    float den0 = 0.f, den1 = 0.f;

    const int NT = NN / KSPLIT / 32;   // 32 tiles

    auto prefetch = [&](int t) {
        if (t < NT) {
            int b = t & 1, m = k0 + t * 32;
            #pragma unroll
            for (int i = tid; i < 256; i += 128) {
                int r = i >> 3, c = (i & 7) << 2;
                size_t g = (size_t)(bt * NN + m + r) * 32 + c;
                cpa16(&sEh[b][r][c], g_Eh32 + g);
                cpa16(&sEl[b][r][c], g_El32 + g);
            }
            #pragma unroll
            for (int i = tid; i < 256; i += 128) {
                int r = i >> 2, c = (i & 3) << 2;
                size_t g = (size_t)(bt * DD + r) * (NN / 2) + (m >> 1) + c;
                cpa16(&sXh[b][r][c], g_Xth + g);
                cpa16(&sXl[b][r][c], g_Xtl + g);
            }
        }
        CP_COMMIT();
    };

    prefetch(0);

    for (int t = 0; t < NT; t++) {
        prefetch(t + 1);
        CP_WAIT1();
        __syncthreads();

        const uint32_t bEh = aEh + (t & 1) * 4608;
        const uint32_t bEl = aEl + (t & 1) * 4608;
        const uint32_t bXh = aXh + (t & 1) * 5120;
        const uint32_t bXl = aXl + (t & 1) * 5120;

        // S = Eq . Ek^T
        float sacc[4][4];
        #pragma unroll
        for (int i = 0; i < 4; i++)
            #pragma unroll
            for (int j = 0; j < 4; j++) sacc[i][j] = 0.f;
        #pragma unroll
        for (int kc = 0; kc < 4; kc++) {
            uint32_t bh0[4], bh1[4], bl0[4], bl1[4];
            ldm4(bh0, bEh + kc * 32);
            ldm4(bh1, bEh + kc * 32 + 16);
            ldm4(bl0, bEl + kc * 32);
            ldm4(bl1, bEl + kc * 32 + 16);
            #pragma unroll
            for (int nt = 0; nt < 4; nt++) {
                mma16816(sacc[nt], Qh[kc], bh0[nt], bh1[nt]);
                mma16816(sacc[nt], Qh[kc], bl0[nt], bl1[nt]);
                mma16816(sacc[nt], Ql[kc], bh0[nt], bh1[nt]);
            }
        }

        // exp + repack C-frag -> A-frag (P hi/lo)
        uint32_t ph[2][4], pl[2][4];
        #pragma unroll
        for (int nt = 0; nt < 4; nt++) {
            float p0 = __expf(sacc[nt][0] - mii0);
            float p1 = __expf(sacc[nt][1] - mii0);
            float p2 = __expf(sacc[nt][2] - mii1);
            float p3 = __expf(sacc[nt][3] - mii1);
            den0 += p0 + p1;
            den1 += p2 + p3;
            uint32_t h01, l01, h23, l23;
            split2(p0, p1, h01, l01);
            split2(p2, p3, h23, l23);
            int kc2 = nt >> 1;
            if ((nt & 1) == 0) {
                ph[kc2][0] = h01; ph[kc2][1] = h23;
                pl[kc2][0] = l01; pl[kc2][1] = l23;
            } else {
                ph[kc2][2] = h01; ph[kc2][3] = h23;
                pl[kc2][2] = l01; pl[kc2][3] = l23;
            }
        }

        // acc += P . X^T  (4-tile d-groups to cap register temporaries)
        #pragma unroll
        for (int kc2 = 0; kc2 < 2; kc2++) {
            #pragma unroll
            for (int dg = 0; dg < 2; dg++) {
                uint32_t h0[4], h1[4], l0[4], l1[4];
                ldm4(h0, bXh + dg * 2560 + kc2 * 32);
                ldm4(h1, bXh + dg * 2560 + kc2 * 32 + 16);
                ldm4(l0, bXl + dg * 2560 + kc2 * 32);
                ldm4(l1, bXl + dg * 2560 + kc2 * 32 + 16);
                #pragma unroll
                for (int i = 0; i < 4; i++) {
                    int dt = dg * 4 + i;
                    mma16816(acc[dt], ph[kc2], h0[i], h1[i]);
                    mma16816(acc[dt], ph[kc2], l0[i], l1[i]);
                    mma16816(acc[dt], pl[kc2], h0[i], h1[i]);
                }
            }
        }
        __syncthreads();
    }

    den0 += __shfl_xor_sync(~0u, den0, 1);
    den0 += __shfl_xor_sync(~0u, den0, 2);
    den1 += __shfl_xor_sync(~0u, den1, 1);
    den1 += __shfl_xor_sync(~0u, den1, 2);

    float* pa = g_pacc[kh];
    #pragma unroll
    for (int dt = 0; dt < 8; dt++) {
        *(float2*)(pa + qrow * 64 + dt * 8 + 2 * tig) =
            make_float2(acc[dt][0], acc[dt][1]);
        *(float2*)(pa + (qrow + 8) * 64 + dt * 8 + 2 * tig) =
            make_float2(acc[dt][2], acc[dt][3]);
    }
    if (tig == 0) {   // lane 4*gr holds row gr's reduced denominator
        g_pden[kh][qrow]     = den0;
        g_pden[kh][qrow + 8] = den1;
    }
}

// ---------------- K3: W = node_emb @ wpool via HMMA (R8 scalar version) -----
__global__ __launch_bounds__(256) void k_wgemm_mma()
{
    __shared__ uint32_t sBh[128][36], sBl[128][36];
    const int tid = threadIdx.x, w = tid >> 5, l = tid & 31;
    const int gr = l >> 2, tig = l & 3;
    const int n0 = blockIdx.y * 128, c0 = blockIdx.x * 128;

    for (int i = tid; i < 4096; i += 256) {
        int c = i >> 5, dp = i & 31;
        sBh[c][dp] = g_Bph[(size_t)(c0 + c) * 32 + dp];
        sBl[c][dp] = g_Bpl[(size_t)(c0 + c) * 32 + dp];
    }

    const size_t ar = (size_t)(n0 + w * 16 + gr);
    uint32_t Ahf[4][4], Alf[4][4];
    #pragma unroll
    for (int kc = 0; kc < 4; kc++) {
        int p0 = kc * 8 + tig, p1 = kc * 8 + 4 + tig;
        Ahf[kc][0] = g_Ah[ar * 32 + p0];
        Ahf[kc][1] = g_Ah[(ar + 8) * 32 + p0];
        Ahf[kc][2] = g_Ah[ar * 32 + p1];
        Ahf[kc][3] = g_Ah[(ar + 8) * 32 + p1];
        Alf[kc][0] = g_Al[ar * 32 + p0];
        Alf[kc][1] = g_Al[(ar + 8) * 32 + p0];
        Alf[kc][2] = g_Al[ar * 32 + p1];
        Alf[kc][3] = g_Al[(ar + 8) * 32 + p1];
    }
    __syncthreads();

    float acc[16][4];
    #pragma unroll
    for (int i = 0; i < 16; i++)
        #pragma unroll
        for (int j = 0; j < 4; j++) acc[i][j] = 0.f;

    #pragma unroll
    for (int ct = 0; ct < 16; ct++) {
        const uint32_t* bh = sBh[ct * 8 + gr];
        const uint32_t* bl = sBl[ct * 8 + gr];
        #pragma unroll
        for (int kc = 0; kc < 4; kc++) {
            uint32_t bh0 = bh[kc * 8 + tig], bh1 = bh[kc * 8 + 4 + tig];
            uint32_t bl0 = bl[kc * 8 + tig], bl1 = bl[kc * 8 + 4 + tig];
            mma16816(acc[ct], Ahf[kc], bh0, bh1);
            mma16816(acc[ct], Ahf[kc], bl0, bl1);
            mma16816(acc[ct], Alf[kc], bh0, bh1);
        }
    }

    #pragma unroll
    for (int ct = 0; ct < 16; ct++) {
        float* p = g_W + ar * WC + c0 + ct * 8 + 2 * tig;
        *(float2*)p            = make_float2(acc[ct][0], acc[ct][1]);
        *(float2*)(p + 8 * WC) = make_float2(acc[ct][2], acc[ct][3]);
    }
}

// ---------------- K5: combine partials + apply hypernet weights ------------
__global__ __launch_bounds__(384) void k_apply(const float* __restrict__ x,
                                               float* __restrict__ out)
{
    __shared__ float Ws[WC];
    __shared__ float xs[BT * DD];
    __shared__ float x2s[BT * DD];
    int n = blockIdx.x;
    const float4* Wn = (const float4*)(g_W + (size_t)n * WC);
    for (int i = threadIdx.x; i < WC / 4; i += 384) ((float4*)Ws)[i] = Wn[i];
    for (int i = threadIdx.x; i < BT * 16; i += 384) {
        int bt = i >> 4, c4 = i & 15;
        size_t base = ((size_t)bt * NN + n) * DD;
        ((float4*)xs)[i] = ((const float4*)(x + base))[c4];
        float den = g_pden[0][bt * NN + n] + g_pden[1][bt * NN + n]
                  + g_pden[2][bt * NN + n] + g_pden[3][bt * NN + n];
        float inv = 1.f / den;
        float4 a = ((const float4*)(g_pacc[0] + base))[c4];
        float4 b = ((const float4*)(g_pacc[1] + base))[c4];
        float4 c = ((const float4*)(g_pacc[2] + base))[c4];
        float4 d = ((const float4*)(g_pacc[3] + base))[c4];
        ((float4*)x2s)[i] = make_float4(
            (a.x + b.x + c.x + d.x) * inv, (a.y + b.y + c.y + d.y) * inv,
            (a.z + b.z + c.z + d.z) * inv, (a.w + b.w + c.w + d.w) * inv);
    }
    __syncthreads();
    int bt = threadIdx.x / 64, o = threadIdx.x & 63;
    float s = g_bias[bt * DD + o];
    #pragma unroll
    for (int i = 0; i < DD; i++) s += xs[bt * DD + i] * Ws[i * DD + o];
    #pragma unroll
    for (int i = 0; i < DD; i++) s += x2s[bt * DD + i] * Ws[4096 + i * DD + o];
    out[((size_t)bt * NN + n) * DD + o] = s;
}

// ---------------------------------------------------------------------------
extern "C" void kernel_launch(void* const* d_in, const int* in_sizes, int n_in,
                              void* d_out, int out_size)
{
    const float* x     = (const float*)d_in[0];
    const float* ne    = (const float*)d_in[1];
    const float* te    = (const float*)d_in[2];
    const float* wpool = (const float*)d_in[3];
    const float* bpool = (const float*)d_in[4];
    const float* gamma = (const float*)d_in[5];
    const float* beta  = (const float*)d_in[6];
    float* out = (float*)d_out;

    // k_attn_mma placed 4th so the ncu capture (launch #4) profiles it.
    k_ln       <<<(BT * NN) / 8, 256>>>(ne, te, gamma, beta);
    k_xsplit   <<<dim3(NN / 64, BT), 256>>>(x);
    k_wpsplit  <<<WC / 32, 256>>>(wpool, te, bpool);
    k_attn_mma <<<dim3(NN / 64, BT, KSPLIT), 128>>>();
    k_wgemm_mma<<<dim3(WC / 128, NN / 128), 256>>>();
    k_apply    <<<NN, 384>>>(x, out);
}